// round 3
// baseline (speedup 1.0000x reference)
#include <cuda_runtime.h>
#include <cuda_bf16.h>
#include <cstdint>

// Problem-size caps (fixed by the dataset)
#define MAXN 100000
#define MAXE 1600000
#define DFEAT 48
#define KITER 10
#define ALPHA 0.1f

// ---------------- scratch (static device memory; no allocations) -------------
__device__ int   g_is64;                 // 1 if edge_index is int64, 0 if int32
__device__ float g_degw[MAXN];
__device__ int   g_deg[MAXN];
__device__ int   g_pos[MAXN];
__device__ int   g_off[MAXN + 1];
__device__ int   g_bsums[256];
__device__ int   g_row[MAXE];
__device__ int   g_col[MAXE];
__device__ int2  g_edge[MAXE];           // (col, norm-as-int-bits), sorted by row
__device__ float g_h0[(size_t)MAXN * DFEAT];
__device__ float g_h1[(size_t)MAXN * DFEAT];

// ---------------- precompute kernels ----------------------------------------

// Detect int64 vs int32 edge_index: for int64 (values < 2^31), the high 32-bit
// word of every entry is 0. For int32 data those words are random indices.
__global__ void k_detect(const int* __restrict__ ei32, int E) {
    __shared__ int any;
    if (threadIdx.x == 0) any = 0;
    __syncthreads();
    int nchk = 1024;
    if (nchk > E) nchk = E;
    for (int i = threadIdx.x; i < nchk; i += blockDim.x)
        if (ei32[2 * i + 1] != 0) any = 1;
    __syncthreads();
    if (threadIdx.x == 0) g_is64 = (any == 0) ? 1 : 0;
}

__global__ void k_zero(float* degw, int* deg, int* pos, int n) {
    int i = blockIdx.x * blockDim.x + threadIdx.x;
    if (i < n) { degw[i] = 0.0f; deg[i] = 0; pos[i] = 0; }
}

// Narrow indices to int32 (dual dtype path), histogram degrees + weighted degrees.
__global__ void k_degw(const void* __restrict__ ei,
                       const float* __restrict__ w,
                       float* __restrict__ degw, int* __restrict__ deg,
                       int* __restrict__ row32, int* __restrict__ col32,
                       int E, int N) {
    int e = blockIdx.x * blockDim.x + threadIdx.x;
    if (e >= E) return;
    int r, c;
    if (g_is64) {
        const long long* p = (const long long*)ei;
        r = (int)p[e];
        c = (int)p[(size_t)E + e];
    } else {
        const int* p = (const int*)ei;
        r = p[e];
        c = p[E + e];
    }
    // defensive clamp: a wrong value can only produce wrong numbers, not a crash
    if (r < 0) r = 0; if (r >= N) r = N - 1;
    if (c < 0) c = 0; if (c >= N) c = N - 1;
    row32[e] = r;
    col32[e] = c;
    atomicAdd(&degw[r], w[e]);
    atomicAdd(&deg[r], 1);
}

// 3-phase exclusive scan of deg -> off
__global__ void k_scan1(const int* __restrict__ deg, int* __restrict__ off,
                        int* __restrict__ bsums, int n) {
    __shared__ int sh[1024];
    int i = blockIdx.x * 1024 + threadIdx.x;
    int v = (i < n) ? deg[i] : 0;
    sh[threadIdx.x] = v;
    __syncthreads();
    for (int d = 1; d < 1024; d <<= 1) {
        int t = 0;
        if (threadIdx.x >= d) t = sh[threadIdx.x - d];
        __syncthreads();
        if (threadIdx.x >= d) sh[threadIdx.x] += t;
        __syncthreads();
    }
    if (i < n) off[i] = sh[threadIdx.x] - v;  // exclusive within block
    if (threadIdx.x == 1023) bsums[blockIdx.x] = sh[1023];
}

__global__ void k_scan2(int* bsums, int nb) {
    if (threadIdx.x == 0 && blockIdx.x == 0) {
        int acc = 0;
        for (int i = 0; i < nb; i++) { int t = bsums[i]; bsums[i] = acc; acc += t; }
    }
}

__global__ void k_scan3(int* __restrict__ off, const int* __restrict__ bsums,
                        int n, int total) {
    int i = blockIdx.x * 1024 + threadIdx.x;
    if (i < n) off[i] += bsums[blockIdx.x];
    if (i == 0) off[n] = total;
}

// Counting-sort scatter: place (col, w/(degw+eps)) into row-sorted slots.
__global__ void k_scatter(const int* __restrict__ row32, const int* __restrict__ col32,
                          const float* __restrict__ w,
                          const float* __restrict__ degw, const int* __restrict__ off,
                          int* __restrict__ pos, int2* __restrict__ ed, int E) {
    int e = blockIdx.x * blockDim.x + threadIdx.x;
    if (e >= E) return;
    int r = row32[e];
    int p = off[r] + atomicAdd(&pos[r], 1);
    float nw = w[e] / (degw[r] + 1e-10f);
    ed[p] = make_int2(col32[e], __float_as_int(nw));
}

// ---------------- propagation mainloop ---------------------------------------
// 16 threads per destination node; lane l owns features {l, l+16, l+32}.
// Edge payload is a single broadcast LDG.64 per edge (same address within group).
__global__ void __launch_bounds__(256)
k_prop(const float* __restrict__ hin, const float* __restrict__ x,
       float* __restrict__ hout,
       const int* __restrict__ off, const int2* __restrict__ ed, int n) {
    int gid = blockIdx.x * blockDim.x + threadIdx.x;
    int node = gid >> 4;
    int lane = gid & 15;
    if (node >= n) return;

    int s = off[node];
    int e = off[node + 1];

    float a0 = 0.0f, a1 = 0.0f, a2 = 0.0f;
    for (int idx = s; idx < e; idx++) {
        int2 t = __ldg(&ed[idx]);                 // broadcast within 16-lane group
        float ww = __int_as_float(t.y);
        const float* hp = hin + (size_t)t.x * DFEAT + lane;
        a0 = fmaf(ww, __ldg(hp),      a0);
        a1 = fmaf(ww, __ldg(hp + 16), a1);
        a2 = fmaf(ww, __ldg(hp + 32), a2);
    }

    size_t o = (size_t)node * DFEAT + lane;
    const float* xp = x + o;
    float* op = hout + o;
    op[0]  = (1.0f - ALPHA) * a0 + ALPHA * __ldg(xp);
    op[16] = (1.0f - ALPHA) * a1 + ALPHA * __ldg(xp + 16);
    op[32] = (1.0f - ALPHA) * a2 + ALPHA * __ldg(xp + 32);
}

// ---------------- launcher ----------------------------------------------------
extern "C" void kernel_launch(void* const* d_in, const int* in_sizes, int n_in,
                              void* d_out, int out_size) {
    const float* x  = (const float*)d_in[0];
    const void*  ei = d_in[1];                 // [2, E], int64 OR int32 (detected)
    const float* ew = (const float*)d_in[2];

    int N = in_sizes[0] / DFEAT;
    int E = in_sizes[2];
    if (N > MAXN) N = MAXN;
    if (E > MAXE) E = MAXE;

    // Resolve scratch symbol addresses (no allocation; capture-safe).
    float *degw, *h0, *h1;
    int *deg, *pos, *off, *bsums, *row32, *col32;
    int2 *edge;
    cudaGetSymbolAddress((void**)&degw,  g_degw);
    cudaGetSymbolAddress((void**)&deg,   g_deg);
    cudaGetSymbolAddress((void**)&pos,   g_pos);
    cudaGetSymbolAddress((void**)&off,   g_off);
    cudaGetSymbolAddress((void**)&bsums, g_bsums);
    cudaGetSymbolAddress((void**)&row32, g_row);
    cudaGetSymbolAddress((void**)&col32, g_col);
    cudaGetSymbolAddress((void**)&edge,  g_edge);
    cudaGetSymbolAddress((void**)&h0,    g_h0);
    cudaGetSymbolAddress((void**)&h1,    g_h1);

    int nb = (N + 1023) / 1024;

    k_detect<<<1, 256>>>((const int*)ei, E);
    k_zero<<<(N + 255) / 256, 256>>>(degw, deg, pos, N);
    k_degw<<<(E + 255) / 256, 256>>>(ei, ew, degw, deg, row32, col32, E, N);
    k_scan1<<<nb, 1024>>>(deg, off, bsums, N);
    k_scan2<<<1, 32>>>(bsums, nb);
    k_scan3<<<nb, 1024>>>(off, bsums, N, E);
    k_scatter<<<(E + 255) / 256, 256>>>(row32, col32, ew, degw, off, pos, edge, E);

    int pblocks = (N * 16 + 255) / 256;
    const float* src = x;
    for (int k = 0; k < KITER; k++) {
        float* dst;
        if (k == KITER - 1)      dst = (float*)d_out;
        else if ((k & 1) == 0)   dst = h0;
        else                     dst = h1;
        k_prop<<<pblocks, 256>>>(src, x, dst, off, edge, N);
        src = dst;
    }
}

// round 4
// speedup vs baseline: 1.1538x; 1.1538x over previous
#include <cuda_runtime.h>
#include <cuda_fp16.h>
#include <cstdint>

// Problem-size caps (fixed by the dataset)
#define MAXN 100000
#define MAXE 1600000
#define DFEAT 48
#define NH2   24          // half2 per node row
#define KITER 10
#define ALPHA 0.1f

// ---------------- scratch (static device memory; no allocations) -------------
__device__ int     g_is64;
__device__ float   g_degw[MAXN];
__device__ int     g_deg[MAXN];
__device__ int     g_pos[MAXN];
__device__ int     g_off[MAXN + 1];
__device__ int     g_bsums[256];
__device__ int     g_row[MAXE];
__device__ int     g_col[MAXE];
__device__ int2    g_edge[MAXE];                    // (col, norm bits), row-sorted
__device__ __half2 g_xh[(size_t)MAXN * NH2];        // x in fp16 (iter-0 input)
__device__ __half2 g_hh0[(size_t)MAXN * NH2];       // ping
__device__ __half2 g_hh1[(size_t)MAXN * NH2];       // pong

// ---------------- precompute kernels ----------------------------------------

// Detect int64 vs int32 edge_index: int64 with values < 2^31 has every odd
// 32-bit word zero; int32 data has random indices there.
__global__ void k_detect(const int* __restrict__ ei32, int E) {
    __shared__ int any;
    if (threadIdx.x == 0) any = 0;
    __syncthreads();
    int nchk = 1024; if (nchk > E) nchk = E;
    for (int i = threadIdx.x; i < nchk; i += blockDim.x)
        if (ei32[2 * i + 1] != 0) any = 1;
    __syncthreads();
    if (threadIdx.x == 0) g_is64 = (any == 0) ? 1 : 0;
}

__global__ void k_zero(float* degw, int* deg, int* pos, int n) {
    int i = blockIdx.x * blockDim.x + threadIdx.x;
    if (i < n) { degw[i] = 0.0f; deg[i] = 0; pos[i] = 0; }
}

// x (fp32) -> half2
__global__ void k_xhalf(const float2* __restrict__ x2, __half2* __restrict__ xh, int n2) {
    int i = blockIdx.x * blockDim.x + threadIdx.x;
    if (i < n2) xh[i] = __float22half2_rn(x2[i]);
}

// Narrow indices (dual dtype), histogram degrees + weighted degrees.
__global__ void k_degw(const void* __restrict__ ei,
                       const float* __restrict__ w,
                       float* __restrict__ degw, int* __restrict__ deg,
                       int* __restrict__ row32, int* __restrict__ col32,
                       int E, int N) {
    int e = blockIdx.x * blockDim.x + threadIdx.x;
    if (e >= E) return;
    int r, c;
    if (g_is64) {
        const long long* p = (const long long*)ei;
        r = (int)p[e];
        c = (int)p[(size_t)E + e];
    } else {
        const int* p = (const int*)ei;
        r = p[e];
        c = p[E + e];
    }
    if (r < 0) r = 0; if (r >= N) r = N - 1;   // crash-proofing only
    if (c < 0) c = 0; if (c >= N) c = N - 1;
    row32[e] = r;
    col32[e] = c;
    atomicAdd(&degw[r], w[e]);
    atomicAdd(&deg[r], 1);
}

// 3-phase exclusive scan of deg -> off
__global__ void k_scan1(const int* __restrict__ deg, int* __restrict__ off,
                        int* __restrict__ bsums, int n) {
    __shared__ int sh[1024];
    int i = blockIdx.x * 1024 + threadIdx.x;
    int v = (i < n) ? deg[i] : 0;
    sh[threadIdx.x] = v;
    __syncthreads();
    for (int d = 1; d < 1024; d <<= 1) {
        int t = 0;
        if (threadIdx.x >= d) t = sh[threadIdx.x - d];
        __syncthreads();
        if (threadIdx.x >= d) sh[threadIdx.x] += t;
        __syncthreads();
    }
    if (i < n) off[i] = sh[threadIdx.x] - v;
    if (threadIdx.x == 1023) bsums[blockIdx.x] = sh[1023];
}

__global__ void k_scan2(int* bsums, int nb) {
    if (threadIdx.x == 0 && blockIdx.x == 0) {
        int acc = 0;
        for (int i = 0; i < nb; i++) { int t = bsums[i]; bsums[i] = acc; acc += t; }
    }
}

__global__ void k_scan3(int* __restrict__ off, const int* __restrict__ bsums,
                        int n, int total) {
    int i = blockIdx.x * 1024 + threadIdx.x;
    if (i < n) off[i] += bsums[blockIdx.x];
    if (i == 0) off[n] = total;
}

// Counting-sort scatter: place (col, w/(degw+eps)) into row-sorted slots.
__global__ void k_scatter(const int* __restrict__ row32, const int* __restrict__ col32,
                          const float* __restrict__ w,
                          const float* __restrict__ degw, const int* __restrict__ off,
                          int* __restrict__ pos, int2* __restrict__ ed, int E) {
    int e = blockIdx.x * blockDim.x + threadIdx.x;
    if (e >= E) return;
    int r = row32[e];
    int p = off[r] + atomicAdd(&pos[r], 1);
    float nw = w[e] / (degw[r] + 1e-10f);
    ed[p] = make_int2(col32[e], __float_as_int(nw));
}

// ---------------- propagation mainloop ---------------------------------------
// 8 lanes per destination node; lane l owns half2 chunks {l, l+8, l+16}.
// Gather: per chunk a group reads 32 contiguous bytes (1 sector); accumulate fp32.
template<bool FINAL>
__global__ void __launch_bounds__(256)
k_proph(const __half2* __restrict__ hin, const float2* __restrict__ x2,
        __half2* __restrict__ hout, float2* __restrict__ fout,
        const int* __restrict__ off, const int2* __restrict__ ed, int n) {
    int gid  = blockIdx.x * blockDim.x + threadIdx.x;
    int node = gid >> 3;
    int lane = gid & 7;
    if (node >= n) return;

    int s = off[node];
    int e = off[node + 1];

    float a0x = 0.f, a0y = 0.f, a1x = 0.f, a1y = 0.f, a2x = 0.f, a2y = 0.f;
    for (int idx = s; idx < e; idx++) {
        int2 t = __ldg(&ed[idx]);                       // broadcast in 8-lane group
        float ww = __int_as_float(t.y);
        const __half2* hp = hin + t.x * NH2 + lane;
        float2 v0 = __half22float2(__ldg(hp));
        float2 v1 = __half22float2(__ldg(hp + 8));
        float2 v2 = __half22float2(__ldg(hp + 16));
        a0x = fmaf(ww, v0.x, a0x);  a0y = fmaf(ww, v0.y, a0y);
        a1x = fmaf(ww, v1.x, a1x);  a1y = fmaf(ww, v1.y, a1y);
        a2x = fmaf(ww, v2.x, a2x);  a2y = fmaf(ww, v2.y, a2y);
    }

    int o = node * NH2 + lane;
    float2 xv0 = __ldg(x2 + o);
    float2 xv1 = __ldg(x2 + o + 8);
    float2 xv2 = __ldg(x2 + o + 16);
    float2 r0 = make_float2(fmaf(1.f - ALPHA, a0x, ALPHA * xv0.x),
                            fmaf(1.f - ALPHA, a0y, ALPHA * xv0.y));
    float2 r1 = make_float2(fmaf(1.f - ALPHA, a1x, ALPHA * xv1.x),
                            fmaf(1.f - ALPHA, a1y, ALPHA * xv1.y));
    float2 r2 = make_float2(fmaf(1.f - ALPHA, a2x, ALPHA * xv2.x),
                            fmaf(1.f - ALPHA, a2y, ALPHA * xv2.y));

    if (FINAL) {
        fout[o]      = r0;
        fout[o + 8]  = r1;
        fout[o + 16] = r2;
    } else {
        hout[o]      = __float22half2_rn(r0);
        hout[o + 8]  = __float22half2_rn(r1);
        hout[o + 16] = __float22half2_rn(r2);
    }
}

// ---------------- launcher ----------------------------------------------------
extern "C" void kernel_launch(void* const* d_in, const int* in_sizes, int n_in,
                              void* d_out, int out_size) {
    const float* x  = (const float*)d_in[0];
    const void*  ei = d_in[1];
    const float* ew = (const float*)d_in[2];

    int N = in_sizes[0] / DFEAT;
    int E = in_sizes[2];
    if (N > MAXN) N = MAXN;
    if (E > MAXE) E = MAXE;

    float *degw; int *deg, *pos, *off, *bsums, *row32, *col32;
    int2 *edge; __half2 *xh, *hh0, *hh1;
    cudaGetSymbolAddress((void**)&degw,  g_degw);
    cudaGetSymbolAddress((void**)&deg,   g_deg);
    cudaGetSymbolAddress((void**)&pos,   g_pos);
    cudaGetSymbolAddress((void**)&off,   g_off);
    cudaGetSymbolAddress((void**)&bsums, g_bsums);
    cudaGetSymbolAddress((void**)&row32, g_row);
    cudaGetSymbolAddress((void**)&col32, g_col);
    cudaGetSymbolAddress((void**)&edge,  g_edge);
    cudaGetSymbolAddress((void**)&xh,    g_xh);
    cudaGetSymbolAddress((void**)&hh0,   g_hh0);
    cudaGetSymbolAddress((void**)&hh1,   g_hh1);

    const float2* x2 = (const float2*)x;
    int nb  = (N + 1023) / 1024;
    int nh2 = N * NH2;

    k_detect<<<1, 256>>>((const int*)ei, E);
    k_zero<<<(N + 255) / 256, 256>>>(degw, deg, pos, N);
    k_xhalf<<<(nh2 + 255) / 256, 256>>>(x2, xh, nh2);
    k_degw<<<(E + 255) / 256, 256>>>(ei, ew, degw, deg, row32, col32, E, N);
    k_scan1<<<nb, 1024>>>(deg, off, bsums, N);
    k_scan2<<<1, 32>>>(bsums, nb);
    k_scan3<<<nb, 1024>>>(off, bsums, N, E);
    k_scatter<<<(E + 255) / 256, 256>>>(row32, col32, ew, degw, off, pos, edge, E);

    int pblocks = (N * 8 + 255) / 256;
    const __half2* src = xh;
    for (int k = 0; k < KITER; k++) {
        if (k == KITER - 1) {
            k_proph<true><<<pblocks, 256>>>(src, x2, nullptr, (float2*)d_out,
                                            off, edge, N);
        } else {
            __half2* dst = ((k & 1) == 0) ? hh0 : hh1;
            k_proph<false><<<pblocks, 256>>>(src, x2, dst, nullptr, off, edge, N);
            src = dst;
        }
    }
}